// round 5
// baseline (speedup 1.0000x reference)
#include <cuda_runtime.h>

typedef unsigned long long u64;
typedef unsigned u32;
#define DI __device__ __forceinline__

// ---------- packed f32x2 helpers (FFMA2 is PTX-only on sm_103a) ----------
DI u64 pack2(float lo, float hi) {
    u64 r;
    asm("mov.b64 %0, {%1, %2};"
        : "=l"(r) : "r"(__float_as_uint(lo)), "r"(__float_as_uint(hi)));
    return r;
}
DI void unpack2(u64 v, u32& lo, u32& hi) {
    asm("mov.b64 {%0, %1}, %2;" : "=r"(lo), "=r"(hi) : "l"(v));
}
DI u64 fma2(u64 a, u64 b, u64 c) {
    u64 d;
    asm("fma.rn.f32x2 %0, %1, %2, %3;" : "=l"(d) : "l"(a), "l"(b), "l"(c));
    return d;
}
DI u32 prmt(u32 a, u32 b, u32 sel) {
    u32 d;
    asm("prmt.b32 %0, %1, %2, %3;" : "=r"(d) : "r"(a), "r"(b), "r"(sel));
    return d;
}
// sign bytes of 4 floats -> one reg [sA,sB,sC,sD] (0xFF where negative)
DI u32 sgn4(u32 a, u32 b, u32 c, u32 d) {
    const u32 ab = prmt(a, b, 0xFBFB);
    const u32 cd = prmt(c, d, 0xFBFB);
    return prmt(ab, cd, 0x5410);
}
DI u32 dp4a(u32 a, u32 b, u32 c) {
    u32 d;
    asm("dp4a.u32.u32 %0, %1, %2, %3;" : "=r"(d) : "r"(a), "r"(b), "r"(c));
    return d;
}

struct SW {                       // smem-resident packed weights
    u64 w1x[8], w1y[8], B1[8];
    u64 w2p[4][8], B2[4];
};

// Two positions (one float4) -> two forces, via forward signs + force table.
DI float4 eval(const float4 p, const SW* __restrict__ W,
               const char* __restrict__ tab) {
    const u64 PX = pack2(p.x, p.z);
    const u64 PY = pack2(p.y, p.w);

    u64 h1[8];
    u32 zl[8], zh[8];
#pragma unroll
    for (int i = 0; i < 8; i++) {
        const u64 z = fma2(W->w1x[i], PX, fma2(W->w1y[i], PY, W->B1[i]));
        unpack2(z, zl[i], zh[i]);
        h1[i] = pack2(fmaxf(__uint_as_float(zl[i]), 0.f),
                      fmaxf(__uint_as_float(zh[i]), 0.f));
    }
    u32 al[4], ah[4];
#pragma unroll
    for (int j = 0; j < 4; j++) {
        u64 acc = W->B2[j];
#pragma unroll
        for (int i = 0; i < 8; i++) acc = fma2(W->w2p[j][i], h1[i], acc);
        unpack2(acc, al[j], ah[j]);
    }

    // sign gather: PRMT byte-mask tree + DP4A bit-pack (depth-4, no chain)
    const u32 K = 0x40201008u;    // byte weights 8,16,32,64
    const u32 ONES = 0x01010101u;

    const u32 ilo = dp4a(sgn4(zl[0], zl[1], zl[2], zl[3]) & K, ONES, 0) |
                    (dp4a(sgn4(zl[4], zl[5], zl[6], zl[7]) & K, ONES, 0) << 4) |
                    (dp4a(sgn4(al[0], al[1], al[2], al[3]) & K, ONES, 0) << 8);
    const u32 ihi = dp4a(sgn4(zh[0], zh[1], zh[2], zh[3]) & K, ONES, 0) |
                    (dp4a(sgn4(zh[4], zh[5], zh[6], zh[7]) & K, ONES, 0) << 4) |
                    (dp4a(sgn4(ah[0], ah[1], ah[2], ah[3]) & K, ONES, 0) << 8);

    const float2 flo = *(const float2*)(tab + ilo);
    const float2 fhi = *(const float2*)(tab + ihi);
    return make_float4(flo.x, flo.y, fhi.x, fhi.y);
}

__global__ void __launch_bounds__(128, 6) toy_force_kernel(
    const float4* __restrict__ pos,
    const float*  __restrict__ W1,   // [8,2]
    const float*  __restrict__ b1,   // [8]
    const float*  __restrict__ W2,   // [4,8]
    const float*  __restrict__ b2,   // [4]
    const float*  __restrict__ W3,   // [2,4]
    float4*       __restrict__ out,
    int npairs)
{
    __shared__ float  u_s[16][8];   // u(m2)_i = sum_{j act} (-v3_j) W2[j][i]
    __shared__ float2 ftab[4096];   // force per 12-bit (m1,m2) sign pattern
    __shared__ SW     Ws;           // packed weights (broadcast LDS in loop)

    const int tid = threadIdx.x;

    // ---- u table: one (m2, i) per thread ----
    {
        const int i = tid & 7, m = tid >> 3;
        float s = 0.f;
#pragma unroll
        for (int j = 0; j < 4; j++) {
            const float v3n = -(__ldg(&W3[j]) + __ldg(&W3[4 + j]));
            if (!((m >> j) & 1)) s += v3n * __ldg(&W2[8 * j + i]);
        }
        u_s[m][i] = s;
    }

    // ---- packed weights into smem (first 2 warps; disjoint from u_s) ----
    if (tid < 8) {
        const int i = tid;
        const float a = __ldg(&W1[2 * i]);
        const float b = __ldg(&W1[2 * i + 1]);
        const float c = __ldg(&b1[i]);
        Ws.w1x[i] = pack2(a, a);
        Ws.w1y[i] = pack2(b, b);
        Ws.B1[i]  = pack2(c, c);
    } else if (tid >= 32 && tid < 68) {
        const int t = tid - 32;
        if (t < 32) {
            const float w = __ldg(&W2[t]);
            Ws.w2p[t >> 3][t & 7] = pack2(w, w);
        } else {
            const float bb = __ldg(&b2[t - 32]);
            Ws.B2[t - 32] = pack2(bb, bb);
        }
    }
    __syncthreads();

    // ---- 4096-entry force table ----
    {
        float w1c[16];
#pragma unroll
        for (int t = 0; t < 16; t++) w1c[t] = __ldg(&W1[t]);
        for (int e = tid; e < 4096; e += blockDim.x) {
            const int m2 = e >> 8;
            float fx = 0.f, fy = 0.f;
#pragma unroll
            for (int i = 0; i < 8; i++) {
                const float msk = ((e >> i) & 1) ? 0.f : 1.f;
                const float ui = msk * u_s[m2][i];
                fx = fmaf(ui, w1c[2 * i], fx);
                fy = fmaf(ui, w1c[2 * i + 1], fy);
            }
            ftab[e] = make_float2(fx, fy);
        }
    }
    __syncthreads();

    const char* tab = (const char*)ftab;
    const SW* W = &Ws;
    const int stride = gridDim.x * blockDim.x;

    // ---- grid-stride, ILP=2, rotating double prefetch ----
    int ka = blockIdx.x * blockDim.x + tid;
    if (ka >= npairs) return;
    int kb = ka + stride;
    bool hb = kb < npairs;

    float4 pa = pos[ka];
    float4 pb = hb ? pos[kb] : pa;

    for (;;) {
        const int kan = ka + 2 * stride;
        const int kbn = kb + 2 * stride;
        const bool han = kan < npairs;
        const bool hbn = hb && (kbn < npairs);
        float4 na, nb;
        if (han) na = pos[kan];
        if (hbn) nb = pos[kbn];

        out[ka] = eval(pa, W, tab);
        if (hb) out[kb] = eval(pb, W, tab);

        if (!han) break;
        pa = na;
        pb = hbn ? nb : na;
        ka = kan;
        kb = kbn;
        hb = hbn;
    }
}

extern "C" void kernel_launch(void* const* d_in, const int* in_sizes, int n_in,
                              void* d_out, int out_size) {
    const float* pos = (const float*)d_in[0];
    const float* W1  = (const float*)d_in[1];
    const float* b1  = (const float*)d_in[2];
    const float* W2  = (const float*)d_in[3];
    const float* b2  = (const float*)d_in[4];
    const float* W3  = (const float*)d_in[5];
    float* out = (float*)d_out;

    const int npairs = in_sizes[0] / 4;   // one float4 = 2 positions

    const int threads = 128;
    const int blocks  = 888;              // 148 SMs x 6 CTAs
    toy_force_kernel<<<blocks, threads>>>(
        (const float4*)pos, W1, b1, W2, b2, W3, (float4*)out, npairs);
}

// round 6
// speedup vs baseline: 1.4620x; 1.4620x over previous
#include <cuda_runtime.h>

typedef unsigned long long u64;
typedef unsigned u32;
#define DI __device__ __forceinline__

// packed (w,w) weight pairs, written idempotently by every CTA:
// [0..7] w1x | [8..15] w1y | [16..23] b1 | [24..55] W2[j*8+i] | [56..59] b2
__device__ u64 gWbuf[60];

// ---------- packed f32x2 helpers (PTX-only on sm_103a) ----------
DI u64 pack2(float lo, float hi) {
    u64 r;
    asm("mov.b64 %0, {%1, %2};"
        : "=l"(r) : "r"(__float_as_uint(lo)), "r"(__float_as_uint(hi)));
    return r;
}
DI void unpack2(u64 v, u32& lo, u32& hi) {
    asm("mov.b64 {%0, %1}, %2;" : "=r"(lo), "=r"(hi) : "l"(v));
}
DI u64 fma2(u64 a, u64 b, u64 c) {
    u64 d;
    asm("fma.rn.f32x2 %0, %1, %2, %3;" : "=l"(d) : "l"(a), "l"(b), "l"(c));
    return d;
}
DI u64 add2(u64 a, u64 b) {
    u64 d;
    asm("add.rn.f32x2 %0, %1, %2;" : "=l"(d) : "l"(a), "l"(b));
    return d;
}
DI u32 prmt(u32 a, u32 b, u32 sel) {
    u32 d;
    asm("prmt.b32 %0, %1, %2, %3;" : "=r"(d) : "r"(a), "r"(b), "r"(sel));
    return d;
}
// sign bytes of 4 floats -> [sA,sB,sC,sD] (0xFF where negative)
DI u32 sgn4(u32 a, u32 b, u32 c, u32 d) {
    const u32 ab = prmt(a, b, 0xFBFB);
    const u32 cd = prmt(c, d, 0xFBFB);
    return prmt(ab, cd, 0x5410);
}
DI u32 dp4a(u32 a, u32 b, u32 c) {
    u32 d;
    asm("dp4a.u32.u32 %0, %1, %2, %3;" : "=r"(d) : "r"(a), "r"(b), "r"(c));
    return d;
}

// Two positions (one float4) -> two forces (as u64 f32x2 each).
// tlo/thi: 256-entry u64 tables, byte-offset = m1half*8 + m2*128.
DI void eval(const float4 p, const u64* __restrict__ gw,
             const char* __restrict__ tlo, const char* __restrict__ thi,
             u64& F0, u64& F1) {
    const u64 PX = pack2(p.x, p.z);
    const u64 PY = pack2(p.y, p.w);

    u64 h1[8];
    u32 zl[8], zh[8];
#pragma unroll
    for (int i = 0; i < 8; i++) {
        const u64 z = fma2(__ldg(&gw[i]), PX,
                           fma2(__ldg(&gw[8 + i]), PY, __ldg(&gw[16 + i])));
        unpack2(z, zl[i], zh[i]);
        h1[i] = pack2(fmaxf(__uint_as_float(zl[i]), 0.f),
                      fmaxf(__uint_as_float(zh[i]), 0.f));
    }
    u32 al[4], ah[4];
#pragma unroll
    for (int j = 0; j < 4; j++) {
        u64 acc = __ldg(&gw[56 + j]);
#pragma unroll
        for (int i = 0; i < 8; i++)
            acc = fma2(__ldg(&gw[24 + 8 * j + i]), h1[i], acc);
        unpack2(acc, al[j], ah[j]);
    }

    const u32 K1 = 0x40201008u;   // byte weights 8,16,32,64 (m1 bits * 8B)
    const u32 K2 = 0x08040201u;   // byte weights 1,2,4,8   (m2 value)
    const u32 ONES = 0x01010101u;

    // position 0 (lo lanes)
    const u32 d1a0 = dp4a(sgn4(zl[0], zl[1], zl[2], zl[3]) & K1, ONES, 0);
    const u32 d1b0 = dp4a(sgn4(zl[4], zl[5], zl[6], zl[7]) & K1, ONES, 0);
    const u32 m2s0 = dp4a(sgn4(al[0], al[1], al[2], al[3]) & K2, ONES, 0) << 7;
    F0 = add2(*(const u64*)(tlo + (d1a0 + m2s0)),
              *(const u64*)(thi + (d1b0 + m2s0)));

    // position 1 (hi lanes)
    const u32 d1a1 = dp4a(sgn4(zh[0], zh[1], zh[2], zh[3]) & K1, ONES, 0);
    const u32 d1b1 = dp4a(sgn4(zh[4], zh[5], zh[6], zh[7]) & K1, ONES, 0);
    const u32 m2s1 = dp4a(sgn4(ah[0], ah[1], ah[2], ah[3]) & K2, ONES, 0) << 7;
    F1 = add2(*(const u64*)(tlo + (d1a1 + m2s1)),
              *(const u64*)(thi + (d1b1 + m2s1)));
}

__global__ void __launch_bounds__(128, 6) toy_force_kernel(
    const float4* __restrict__ pos,
    const float*  __restrict__ W1,   // [8,2]
    const float*  __restrict__ b1,   // [8]
    const float*  __restrict__ W2,   // [4,8]
    const float*  __restrict__ b2,   // [4]
    const float*  __restrict__ W3,   // [2,4]
    float4*       __restrict__ out,
    int npairs)
{
    __shared__ float u_s[16][8];   // u(m2)_i = sum_{j active} (-v3_j) W2[j][i]
    __shared__ u64 tlo[256];       // f contribution of m1[0:4] given m2
    __shared__ u64 thi[256];       // f contribution of m1[4:8] given m2

    const int tid = threadIdx.x;

    // ---- u table: one (m2, i) per thread ----
    {
        const int i = tid & 7, m = tid >> 3;
        float s = 0.f;
#pragma unroll
        for (int j = 0; j < 4; j++) {
            const float v3n = -(__ldg(&W3[j]) + __ldg(&W3[4 + j]));  // -grad fold
            if (!((m >> j) & 1)) s += v3n * __ldg(&W2[8 * j + i]);
        }
        u_s[m][i] = s;
    }

    // ---- idempotent global weight pack (every CTA writes same values) ----
    if (tid < 60) {
        float w;
        if (tid < 8)        w = __ldg(&W1[2 * tid]);          // w1x
        else if (tid < 16)  w = __ldg(&W1[2 * (tid - 8) + 1]);// w1y
        else if (tid < 24)  w = __ldg(&b1[tid - 16]);         // b1
        else if (tid < 56)  w = __ldg(&W2[tid - 24]);         // W2
        else                w = __ldg(&b2[tid - 56]);         // b2
        gWbuf[tid] = pack2(w, w);
    }
    __syncthreads();

    // ---- split force tables: 512 entries, 4 per thread ----
    {
        float w1c[16];
#pragma unroll
        for (int t = 0; t < 16; t++) w1c[t] = __ldg(&W1[t]);
        for (int e = tid; e < 512; e += blockDim.x) {
            const bool hi = e >= 256;
            const int ent = e & 255;
            const int m1h = ent & 15, m2 = ent >> 4;
            const int base = hi ? 4 : 0;
            float fx = 0.f, fy = 0.f;
#pragma unroll
            for (int k = 0; k < 4; k++) {
                const int i = base + k;
                const float msk = ((m1h >> k) & 1) ? 0.f : 1.f;
                const float ui = msk * u_s[m2][i];
                fx = fmaf(ui, w1c[2 * i], fx);
                fy = fmaf(ui, w1c[2 * i + 1], fy);
            }
            (hi ? thi : tlo)[ent] = pack2(fx, fy);
        }
    }
    __syncthreads();

    const char* tl = (const char*)tlo;
    const char* th = (const char*)thi;
    const u64* gw = gWbuf;
    const int stride = gridDim.x * blockDim.x;

    // ---- grid-stride, ILP=2, rotating double prefetch ----
    int ka = blockIdx.x * blockDim.x + tid;
    if (ka >= npairs) return;
    int kb = ka + stride;
    bool hb = kb < npairs;

    float4 pa = pos[ka];
    float4 pb = hb ? pos[kb] : pa;

    for (;;) {
        const int kan = ka + 2 * stride;
        const int kbn = kb + 2 * stride;
        const bool han = kan < npairs;
        const bool hbn = hb && (kbn < npairs);
        float4 na, nb;
        if (han) na = pos[kan];
        if (hbn) nb = pos[kbn];

        u64 F0, F1;
        eval(pa, gw, tl, th, F0, F1);
        *(ulonglong2*)&out[ka] = make_ulonglong2(F0, F1);
        if (hb) {
            u64 G0, G1;
            eval(pb, gw, tl, th, G0, G1);
            *(ulonglong2*)&out[kb] = make_ulonglong2(G0, G1);
        }

        if (!han) break;
        pa = na;
        pb = hbn ? nb : na;
        ka = kan;
        kb = kbn;
        hb = hbn;
    }
}

extern "C" void kernel_launch(void* const* d_in, const int* in_sizes, int n_in,
                              void* d_out, int out_size) {
    const float* pos = (const float*)d_in[0];
    const float* W1  = (const float*)d_in[1];
    const float* b1  = (const float*)d_in[2];
    const float* W2  = (const float*)d_in[3];
    const float* b2  = (const float*)d_in[4];
    const float* W3  = (const float*)d_in[5];
    float* out = (float*)d_out;

    const int npairs = in_sizes[0] / 4;   // one float4 = 2 positions

    const int threads = 128;
    const int blocks  = 888;              // 148 SMs x 6 CTAs
    toy_force_kernel<<<blocks, threads>>>(
        (const float4*)pos, W1, b1, W2, b2, W3, (float4*)out, npairs);
}

// round 7
// speedup vs baseline: 2.1381x; 1.4625x over previous
#include <cuda_runtime.h>

typedef unsigned long long u64;
typedef unsigned u32;
#define DI __device__ __forceinline__

// gathered weights: [0:16) W1 | [16:24) b1 | [24:56) W2 | [56:60) b2 | [60:68) W3
__device__   float gAll[68];
__constant__ float cAll[68];

// ---------- packed f32x2 helpers (PTX-only on sm_103a) ----------
DI u64 pack2(float lo, float hi) {
    u64 r;
    asm("mov.b64 %0, {%1, %2};"
        : "=l"(r) : "r"(__float_as_uint(lo)), "r"(__float_as_uint(hi)));
    return r;
}
DI void unpack2(u64 v, u32& lo, u32& hi) {
    asm("mov.b64 {%0, %1}, %2;" : "=r"(lo), "=r"(hi) : "l"(v));
}
DI u64 fma2(u64 a, u64 b, u64 c) {
    u64 d;
    asm("fma.rn.f32x2 %0, %1, %2, %3;" : "=l"(d) : "l"(a), "l"(b), "l"(c));
    return d;
}
DI u64 add2(u64 a, u64 b) {
    u64 d;
    asm("add.rn.f32x2 %0, %1, %2;" : "=l"(d) : "l"(a), "l"(b));
    return d;
}
DI u32 prmt(u32 a, u32 b, u32 sel) {
    u32 d;
    asm("prmt.b32 %0, %1, %2, %3;" : "=r"(d) : "r"(a), "r"(b), "r"(sel));
    return d;
}
// sign bytes of 4 floats -> [sA,sB,sC,sD] (0xFF where negative)
DI u32 sgn4(u32 a, u32 b, u32 c, u32 d) {
    const u32 ab = prmt(a, b, 0xFBFB);
    const u32 cd = prmt(c, d, 0xFBFB);
    return prmt(ab, cd, 0x5410);
}
DI u32 dp4a(u32 a, u32 b, u32 c) {
    u32 d;
    asm("dp4a.u32.u32 %0, %1, %2, %3;" : "=r"(d) : "r"(a), "r"(b), "r"(c));
    return d;
}

// weight source: true -> constant bank (uniform datapath), false -> global
template <bool C>
struct Src {
    const float* g;
    DI float w(int i) const { return C ? cAll[i] : __ldg(&g[i]); }
    DI u64  wp(int i) const { const float v = w(i); return pack2(v, v); }
};

// Two positions (one float4) -> two forces (u64 f32x2 each).
// tlo/thi: 256-entry u64 tables, byte-offset = m1half*8 + m2*128.
template <bool C>
DI void eval(const float4 p, const Src<C> S,
             const char* __restrict__ tlo, const char* __restrict__ thi,
             u64& F0, u64& F1) {
    const u64 PX = pack2(p.x, p.z);
    const u64 PY = pack2(p.y, p.w);

    u64 h1[8];
    u32 zl[8], zh[8];
#pragma unroll
    for (int i = 0; i < 8; i++) {
        const u64 z = fma2(S.wp(2 * i), PX,
                           fma2(S.wp(2 * i + 1), PY, S.wp(16 + i)));
        unpack2(z, zl[i], zh[i]);
        h1[i] = pack2(fmaxf(__uint_as_float(zl[i]), 0.f),
                      fmaxf(__uint_as_float(zh[i]), 0.f));
    }
    u32 al[4], ah[4];
#pragma unroll
    for (int j = 0; j < 4; j++) {
        u64 acc = S.wp(56 + j);
#pragma unroll
        for (int i = 0; i < 8; i++)
            acc = fma2(S.wp(24 + 8 * j + i), h1[i], acc);
        unpack2(acc, al[j], ah[j]);
    }

    const u32 K1 = 0x40201008u;   // byte weights 8,16,32,64 (m1 bits * 8B)
    const u32 K2 = 0x08040201u;   // byte weights 1,2,4,8   (m2 value)
    const u32 ONES = 0x01010101u;

    const u32 d1a0 = dp4a(sgn4(zl[0], zl[1], zl[2], zl[3]) & K1, ONES, 0);
    const u32 d1b0 = dp4a(sgn4(zl[4], zl[5], zl[6], zl[7]) & K1, ONES, 0);
    const u32 m2s0 = dp4a(sgn4(al[0], al[1], al[2], al[3]) & K2, ONES, 0) << 7;
    F0 = add2(*(const u64*)(tlo + (d1a0 + m2s0)),
              *(const u64*)(thi + (d1b0 + m2s0)));

    const u32 d1a1 = dp4a(sgn4(zh[0], zh[1], zh[2], zh[3]) & K1, ONES, 0);
    const u32 d1b1 = dp4a(sgn4(zh[4], zh[5], zh[6], zh[7]) & K1, ONES, 0);
    const u32 m2s1 = dp4a(sgn4(ah[0], ah[1], ah[2], ah[3]) & K2, ONES, 0) << 7;
    F1 = add2(*(const u64*)(tlo + (d1a1 + m2s1)),
              *(const u64*)(thi + (d1b1 + m2s1)));
}

// one-warp gather: 5 arrays -> contiguous gAll
__global__ void gather_weights(const float* __restrict__ W1,
                               const float* __restrict__ b1,
                               const float* __restrict__ W2,
                               const float* __restrict__ b2,
                               const float* __restrict__ W3) {
    const int t = threadIdx.x;
    if (t < 16)       gAll[t] = W1[t];
    else if (t < 24)  gAll[t] = b1[t - 16];
    else if (t < 56)  gAll[t] = W2[t - 24];
    else if (t < 60)  gAll[t] = b2[t - 56];
    else if (t < 68)  gAll[t] = W3[t - 60];
}

template <bool C>
__global__ void __launch_bounds__(128, 8) toy_force_kernel(
    const float4* __restrict__ pos,
    const float*  __restrict__ gw,   // gathered 68-float weight buffer
    float4*       __restrict__ out,
    int npairs)
{
    __shared__ float u_s[16][8];   // u(m2)_i = sum_{j act} (-v3_j) W2[j][i]
    __shared__ u64 tlo[256];       // f contribution of m1[0:4] given m2
    __shared__ u64 thi[256];       // f contribution of m1[4:8] given m2

    Src<C> S{gw};
    const int tid = threadIdx.x;

    // ---- u table: one (m2, i) per thread ----
    {
        const int i = tid & 7, m = tid >> 3;
        float s = 0.f;
#pragma unroll
        for (int j = 0; j < 4; j++) {
            const float v3n = -(S.w(60 + j) + S.w(64 + j));   // fold -grad
            if (!((m >> j) & 1)) s += v3n * S.w(24 + 8 * j + i);
        }
        u_s[m][i] = s;
    }
    __syncthreads();

    // ---- split force tables: 512 entries ----
    for (int e = tid; e < 512; e += blockDim.x) {
        const bool hi = e >= 256;
        const int ent = e & 255;
        const int m1h = ent & 15, m2 = ent >> 4;
        const int base = hi ? 4 : 0;
        float fx = 0.f, fy = 0.f;
#pragma unroll
        for (int k = 0; k < 4; k++) {
            const int i = base + k;
            const float msk = ((m1h >> k) & 1) ? 0.f : 1.f;
            const float ui = msk * u_s[m2][i];
            fx = fmaf(ui, S.w(2 * i), fx);
            fy = fmaf(ui, S.w(2 * i + 1), fy);
        }
        (hi ? thi : tlo)[ent] = pack2(fx, fy);
    }
    __syncthreads();

    const char* tl = (const char*)tlo;
    const char* th = (const char*)thi;
    const int stride = gridDim.x * blockDim.x;

    // ---- grid-stride, ILP=2, rotating double prefetch ----
    int ka = blockIdx.x * blockDim.x + tid;
    if (ka >= npairs) return;
    int kb = ka + stride;
    bool hb = kb < npairs;

    float4 pa = pos[ka];
    float4 pb = hb ? pos[kb] : pa;

    for (;;) {
        const int kan = ka + 2 * stride;
        const int kbn = kb + 2 * stride;
        const bool han = kan < npairs;
        const bool hbn = hb && (kbn < npairs);
        float4 na, nb;
        if (han) na = pos[kan];
        if (hbn) nb = pos[kbn];

        u64 F0, F1;
        eval<C>(pa, S, tl, th, F0, F1);
        *(ulonglong2*)&out[ka] = make_ulonglong2(F0, F1);
        if (hb) {
            u64 G0, G1;
            eval<C>(pb, S, tl, th, G0, G1);
            *(ulonglong2*)&out[kb] = make_ulonglong2(G0, G1);
        }

        if (!han) break;
        pa = na;
        pb = hbn ? nb : na;
        ka = kan;
        kb = kbn;
        hb = hbn;
    }
}

extern "C" void kernel_launch(void* const* d_in, const int* in_sizes, int n_in,
                              void* d_out, int out_size) {
    const float* pos = (const float*)d_in[0];
    const float* W1  = (const float*)d_in[1];
    const float* b1  = (const float*)d_in[2];
    const float* W2  = (const float*)d_in[3];
    const float* b2  = (const float*)d_in[4];
    const float* W3  = (const float*)d_in[5];
    float* out = (float*)d_out;

    const int npairs = in_sizes[0] / 4;   // one float4 = 2 positions

    // 1) gather 68 weights into one contiguous device buffer (kernel node)
    gather_weights<<<1, 68>>>(W1, b1, W2, b2, W3);

    // 2) single D2D memcpy node into the constant bank
    void* gptr = nullptr;
    bool ok = cudaGetSymbolAddress(&gptr, gAll) == cudaSuccess;
    if (ok)
        ok = cudaMemcpyToSymbolAsync(cAll, gptr, 68 * sizeof(float), 0,
                                     cudaMemcpyDeviceToDevice, 0) == cudaSuccess;

    const int threads = 128;
    const int blocks  = 1184;             // 148 SMs x 8 CTAs
    if (ok) {
        toy_force_kernel<true><<<blocks, threads>>>(
            (const float4*)pos, gptr ? (const float*)gptr : W1,
            (float4*)out, npairs);
    } else {
        // fallback: read weights straight from the gathered global buffer
        toy_force_kernel<false><<<blocks, threads>>>(
            (const float4*)pos, (const float*)gptr, (float4*)out, npairs);
    }
}